// round 13
// baseline (speedup 1.0000x reference)
#include <cuda_runtime.h>
#include <cuda_fp16.h>
#include <cstdint>
#include <math.h>

// ============================================================================
// Shapes
// ============================================================================
#define M_TOTAL 8192
#define N_EMBD  1024
#define N_STATE 4096

// CTA 128x128x64, 8 warps of 64x32, 2 CTAs/SM, persistent w/ continuous pipeline
#define CTA_M  128
#define CTA_N  128
#define CTA_K  64                   // halves per k-tile (4 k-steps of 16)
#define STAGES 3
#define GRID_CTAS 296               // 2 per SM x 148 SMs

#define PITCH_B   144               // bytes per smem row (64 halves + 16B pad)
#define ROWS_PER_STAGE (CTA_M + CTA_N)              // 256
#define STAGE_BYTES    (ROWS_PER_STAGE * PITCH_B)   // 36864
#define SMEM_BYTES     (STAGES * STAGE_BYTES)       // 110592

// Scratch (static; no allocation allowed)
__device__ __half g_Xh [(size_t)M_TOTAL * N_EMBD];       // 16 MB
__device__ __half g_W1t[(size_t)N_STATE * N_EMBD];       //  8 MB  [N][K]
__device__ __half g_W2t[(size_t)N_EMBD * N_STATE];       //  8 MB  [N][K]
__device__ __half g_H  [(size_t)M_TOTAL * N_STATE];      // 64 MB

// ============================================================================
// PTX helpers
// ============================================================================
__device__ __forceinline__ uint32_t smem_u32(const void* p) {
    uint32_t a;
    asm("{ .reg .u64 t; cvta.to.shared.u64 t, %1; cvt.u32.u64 %0, t; }" : "=r"(a) : "l"(p));
    return a;
}
__device__ __forceinline__ void cp_async16(uint32_t dst, const void* src) {
    asm volatile("cp.async.cg.shared.global [%0], [%1], 16;" :: "r"(dst), "l"(src));
}
__device__ __forceinline__ void cp_commit() {
    asm volatile("cp.async.commit_group;" ::: "memory");
}
template <int N>
__device__ __forceinline__ void cp_wait() {
    asm volatile("cp.async.wait_group %0;" :: "n"(N) : "memory");
}
__device__ __forceinline__ void ldsm_x4(uint32_t* r, uint32_t addr) {
    asm volatile("ldmatrix.sync.aligned.m8n8.x4.shared.b16 {%0,%1,%2,%3}, [%4];"
        : "=r"(r[0]), "=r"(r[1]), "=r"(r[2]), "=r"(r[3]) : "r"(addr));
}
__device__ __forceinline__ void mma_f16(float* c, const uint32_t* a, const uint32_t* b) {
    asm volatile(
        "mma.sync.aligned.m16n8k16.row.col.f32.f16.f16.f32 "
        "{%0,%1,%2,%3}, {%4,%5,%6,%7}, {%8,%9}, {%0,%1,%2,%3};"
        : "+f"(c[0]), "+f"(c[1]), "+f"(c[2]), "+f"(c[3])
        : "r"(a[0]), "r"(a[1]), "r"(a[2]), "r"(a[3]), "r"(b[0]), "r"(b[1]));
}
__device__ __forceinline__ float gelu_exact(float x) {
    return 0.5f * x * (1.0f + erff(x * 0.70710678118654752f));
}

// ============================================================================
// Fused prepass (ONE launch) — unchanged from R12 champion
// ============================================================================
#define XB_BLOCKS  2048
#define W1_BX (N_STATE / 32)
#define W1_BY (N_EMBD  / 32)
#define W2_BX (N_EMBD  / 32)
#define W2_BY (N_STATE / 32)
#define W1_BLOCKS (W1_BX * W1_BY)
#define W2_BLOCKS (W2_BX * W2_BY)
#define PRE_BLOCKS (XB_BLOCKS + W1_BLOCKS + W2_BLOCKS)

__device__ __forceinline__ void transpose_tile32(const float* __restrict__ in,
                                                 __half* __restrict__ out,
                                                 int rows, int cols, int bx, int by,
                                                 int tx, int ty) {
    __shared__ float tile[32][33];
    for (int r = ty; r < 32; r += 8)
        tile[r][tx] = in[(size_t)(by + r) * cols + bx + tx];
    __syncthreads();
    for (int r = ty; r < 32; r += 8)
        out[(size_t)(bx + r) * rows + by + tx] = __float2half_rn(tile[tx][r]);
}

__global__ void __launch_bounds__(256, 2)
prepass_kernel(const float* __restrict__ x,  __half* __restrict__ Xh,
               const float* __restrict__ w1, __half* __restrict__ W1t,
               const float* __restrict__ w2, __half* __restrict__ W2t)
{
    const int b  = blockIdx.x;
    const int tx = threadIdx.x;
    const int ty = threadIdx.y;
    const int tid = ty * 32 + tx;

    if (b < XB_BLOCKS) {
        const int n4 = (M_TOTAL * N_EMBD) / 4;
        const int stride = XB_BLOCKS * 256;
        for (int i = b * 256 + tid; i < n4; i += stride) {
            float4 v = reinterpret_cast<const float4*>(x)[i];
            __half2* o = reinterpret_cast<__half2*>(Xh) + 2 * i;
            o[0] = __floats2half2_rn(v.x, v.y);
            o[1] = __floats2half2_rn(v.z, v.w);
        }
    } else if (b < XB_BLOCKS + W1_BLOCKS) {
        const int bb = b - XB_BLOCKS;
        transpose_tile32(w1, W1t, N_EMBD, N_STATE, (bb % W1_BX) * 32, (bb / W1_BX) * 32, tx, ty);
    } else {
        const int bb = b - XB_BLOCKS - W1_BLOCKS;
        transpose_tile32(w2, W2t, N_STATE, N_EMBD, (bb % W2_BX) * 32, (bb / W2_BX) * 32, tx, ty);
    }
}

// ============================================================================
// Persistent GEMM with continuous cross-tile cp.async pipeline.
//   out[M,N] = op(A[M,K] @ Bt[N,K]^T + bias).
//   When a tile's prefetch index passes its last k-tile, it loads the NEXT
//   tile's k-tiles 0..1 — the pipeline never drains; the inter-tile stage
//   refill overlaps the epilogue. Stage rotation continues mod 3 across tiles.
// ============================================================================
template <int DO_GELU, int TX_LOG2, int NKT>
__global__ void __launch_bounds__(256, 2)
mlp_gemm_h(const __half* __restrict__ A, const __half* __restrict__ Bt,
           const float* __restrict__ bias, void* __restrict__ outp,
           int K, int N, int numTiles)
{
    extern __shared__ __half smem[];
    const uint32_t smem_base = smem_u32(smem);

    const int tid  = threadIdx.x;
    const int wid  = tid >> 5;
    const int lane = tid & 31;
    const int g    = lane >> 2;
    const int t4   = lane & 3;
    const int wm   = wid & 1;           // 2 warps in M (64 rows)
    const int wn   = wid >> 1;          // 4 warps in N (32 cols)

    // per-lane ldmatrix offsets (bytes)
    const int mi = lane >> 3;
    const int r8 = lane & 7;
    const uint32_t a_lane = (uint32_t)(((mi & 1) * 8 + r8) * PITCH_B + (mi >> 1) * 16);
    const uint32_t b_lane = (uint32_t)(((mi >> 1) * 8 + r8) * PITCH_B + (mi & 1) * 16);
    const uint32_t aw_base = smem_base + (uint32_t)(wm * 64) * PITCH_B + a_lane;
    const uint32_t bw_base = smem_base + (uint32_t)(CTA_M + wn * 32) * PITCH_B + b_lane;

    auto load_stage = [&](int s, int m0, int n0, int kt) {
        uint32_t dstS = smem_base + (uint32_t)s * STAGE_BYTES;
        const __half* aG = A  + (size_t)m0 * K + kt * CTA_K;
        const __half* bG = Bt + (size_t)n0 * K + kt * CTA_K;
        #pragma unroll
        for (int i = 0; i < 8; i++) {
            int c   = tid + i * 256;
            int row = c >> 3, ch = c & 7;
            const __half* src = (row < CTA_M)
                ? aG + (size_t)row * K + ch * 8
                : bG + (size_t)(row - CTA_M) * K + ch * 8;
            cp_async16(dstS + (uint32_t)row * PITCH_B + (uint32_t)ch * 16, src);
        }
    };

    const int G = gridDim.x;
    int t = blockIdx.x;
    if (t >= numTiles) return;

    // prologue: first tile's k-tiles 0,1
    {
        const int m0 = (t >> TX_LOG2) * CTA_M;
        const int n0 = (t & ((1 << TX_LOG2) - 1)) * CTA_N;
        load_stage(0, m0, n0, 0); cp_commit();
        load_stage(1, m0, n0, 1); cp_commit();
    }

    int s_cur = 0, s_next = 2;           // continues across tiles (mod 3)
    for (; t < numTiles; t += G) {
        const int m0 = (t >> TX_LOG2) * CTA_M;
        const int n0 = (t & ((1 << TX_LOG2) - 1)) * CTA_N;
        const int tn = t + G;
        const bool has_next = tn < numTiles;
        const int m0n = has_next ? (tn >> TX_LOG2) * CTA_M : 0;
        const int n0n = has_next ? (tn & ((1 << TX_LOG2) - 1)) * CTA_N : 0;

        float acc[4][4][4];
        #pragma unroll
        for (int mt = 0; mt < 4; mt++)
            #pragma unroll
            for (int ni = 0; ni < 4; ni++)
                #pragma unroll
                for (int j = 0; j < 4; j++) acc[mt][ni][j] = 0.0f;

        for (int kt = 0; kt < NKT; kt++) {
            cp_wait<STAGES - 2>();
            __syncthreads();

            const int lk = kt + 2;
            if (lk < NKT)          load_stage(s_next, m0,  n0,  lk);
            else if (has_next)     load_stage(s_next, m0n, n0n, lk - NKT);
            cp_commit();
            if (++s_next == STAGES) s_next = 0;

            const uint32_t aw = aw_base + (uint32_t)s_cur * STAGE_BYTES;
            const uint32_t bw = bw_base + (uint32_t)s_cur * STAGE_BYTES;
            if (++s_cur == STAGES) s_cur = 0;

            #pragma unroll
            for (int ks = 0; ks < 4; ks++) {
                const uint32_t ko = (uint32_t)(ks * 32);      // 16 halves = 32B
                uint32_t af[4][4];
                #pragma unroll
                for (int mt = 0; mt < 4; mt++)
                    ldsm_x4(af[mt], aw + ko + (uint32_t)(mt * 16) * PITCH_B);
                uint32_t bf[4][2];
                #pragma unroll
                for (int np = 0; np < 2; np++) {
                    uint32_t q[4];
                    ldsm_x4(q, bw + ko + (uint32_t)(np * 16) * PITCH_B);
                    bf[np * 2][0]     = q[0]; bf[np * 2][1]     = q[1];
                    bf[np * 2 + 1][0] = q[2]; bf[np * 2 + 1][1] = q[3];
                }
                #pragma unroll
                for (int mt = 0; mt < 4; mt++)
                    #pragma unroll
                    for (int ni = 0; ni < 4; ni++)
                        mma_f16(acc[mt][ni], af[mt], bf[ni]);
            }
        }

        // -------- epilogue (registers + gmem only; overlaps next-tile fills) ----
        #pragma unroll
        for (int mt = 0; mt < 4; mt++) {
            const int row = m0 + wm * 64 + mt * 16 + g;
            #pragma unroll
            for (int ni = 0; ni < 4; ni++) {
                const int col = n0 + wn * 32 + ni * 8 + 2 * t4;
                const float2 bv = *reinterpret_cast<const float2*>(bias + col);
                float x0 = acc[mt][ni][0] + bv.x;
                float x1 = acc[mt][ni][1] + bv.y;
                float x2 = acc[mt][ni][2] + bv.x;
                float x3 = acc[mt][ni][3] + bv.y;
                if (DO_GELU) {
                    __half* out = (__half*)outp;
                    __half2 h01 = __floats2half2_rn(gelu_exact(x0), gelu_exact(x1));
                    __half2 h23 = __floats2half2_rn(gelu_exact(x2), gelu_exact(x3));
                    *reinterpret_cast<__half2*>(out + (size_t)row * N + col)       = h01;
                    *reinterpret_cast<__half2*>(out + (size_t)(row + 8) * N + col) = h23;
                } else {
                    float* out = (float*)outp;
                    float2 v01 = {x0, x1}, v23 = {x2, x3};
                    *reinterpret_cast<float2*>(out + (size_t)row * N + col)       = v01;
                    *reinterpret_cast<float2*>(out + (size_t)(row + 8) * N + col) = v23;
                }
            }
        }
        // no barrier needed: next iteration's cp_wait + __syncthreads provides it
    }
}

// ============================================================================
// Host
// ============================================================================
extern "C" void kernel_launch(void* const* d_in, const int* in_sizes, int n_in,
                              void* d_out, int out_size) {
    const float* x  = (const float*)d_in[0];
    const float* w1 = (const float*)d_in[1];
    const float* b1 = (const float*)d_in[2];
    const float* w2 = (const float*)d_in[3];
    const float* b2 = (const float*)d_in[4];
    float* out = (float*)d_out;

    __half *Xh, *W1t, *W2t, *H;
    cudaGetSymbolAddress((void**)&Xh,  g_Xh);
    cudaGetSymbolAddress((void**)&W1t, g_W1t);
    cudaGetSymbolAddress((void**)&W2t, g_W2t);
    cudaGetSymbolAddress((void**)&H,   g_H);

    cudaFuncSetAttribute((const void*)mlp_gemm_h<1, 5, 16>,
                         cudaFuncAttributeMaxDynamicSharedMemorySize, SMEM_BYTES);
    cudaFuncSetAttribute((const void*)mlp_gemm_h<0, 3, 64>,
                         cudaFuncAttributeMaxDynamicSharedMemorySize, SMEM_BYTES);

    // Fused prepass (one launch)
    prepass_kernel<<<PRE_BLOCKS, dim3(32, 8)>>>(x, Xh, w1, W1t, w2, W2t);

    // GEMM1: H = fp16(GELU(X @ W1 + b1)) — 2048 tiles (32 n-tiles), NKT=16
    mlp_gemm_h<1, 5, 16><<<GRID_CTAS, 256, SMEM_BYTES>>>(
        Xh, W1t, b1, H, N_EMBD, N_STATE, (M_TOTAL / CTA_M) * (N_STATE / CTA_N));

    // GEMM2: out = H @ W2 + b2 — 512 tiles (8 n-tiles), NKT=64
    mlp_gemm_h<0, 3, 64><<<GRID_CTAS, 256, SMEM_BYTES>>>(
        H, W2t, b2, out, N_STATE, N_EMBD, (M_TOTAL / CTA_M) * (N_EMBD / CTA_N));
}

// round 14
// speedup vs baseline: 1.0910x; 1.0910x over previous
#include <cuda_runtime.h>
#include <cuda_fp16.h>
#include <cstdint>
#include <math.h>

// ============================================================================
// Shapes
// ============================================================================
#define M_TOTAL 8192
#define N_EMBD  1024
#define N_STATE 4096

// CTA 128x128x64, 8 warps of 64x32, 2 CTAs/SM  (R6/R12 champion config)
#define CTA_M  128
#define CTA_N  128
#define CTA_K  64                   // halves per k-tile (4 k-steps of 16)
#define STAGES 3

#define PITCH_B   144               // bytes per smem row (64 halves + 16B pad)
#define ROWS_PER_STAGE (CTA_M + CTA_N)              // 256
#define STAGE_BYTES    (ROWS_PER_STAGE * PITCH_B)   // 36864
#define SMEM_BYTES     (STAGES * STAGE_BYTES)       // 110592

// Scratch (static; no allocation allowed)
__device__ __half g_Xh [(size_t)M_TOTAL * N_EMBD];       // 16 MB
__device__ __half g_W1t[(size_t)N_STATE * N_EMBD];       //  8 MB  [N][K]
__device__ __half g_W2t[(size_t)N_EMBD * N_STATE];       //  8 MB  [N][K]
__device__ __half g_H  [(size_t)M_TOTAL * N_STATE];      // 64 MB

// ============================================================================
// PTX helpers
// ============================================================================
__device__ __forceinline__ uint32_t smem_u32(const void* p) {
    uint32_t a;
    asm("{ .reg .u64 t; cvta.to.shared.u64 t, %1; cvt.u32.u64 %0, t; }" : "=r"(a) : "l"(p));
    return a;
}
__device__ __forceinline__ void cp_async16(uint32_t dst, const void* src) {
    asm volatile("cp.async.cg.shared.global [%0], [%1], 16;" :: "r"(dst), "l"(src));
}
__device__ __forceinline__ void cp_commit() {
    asm volatile("cp.async.commit_group;" ::: "memory");
}
template <int N>
__device__ __forceinline__ void cp_wait() {
    asm volatile("cp.async.wait_group %0;" :: "n"(N) : "memory");
}
__device__ __forceinline__ void ldsm_x4(uint32_t* r, uint32_t addr) {
    asm volatile("ldmatrix.sync.aligned.m8n8.x4.shared.b16 {%0,%1,%2,%3}, [%4];"
        : "=r"(r[0]), "=r"(r[1]), "=r"(r[2]), "=r"(r[3]) : "r"(addr));
}
__device__ __forceinline__ void mma_f16(float* c, const uint32_t* a, const uint32_t* b) {
    asm volatile(
        "mma.sync.aligned.m16n8k16.row.col.f32.f16.f16.f32 "
        "{%0,%1,%2,%3}, {%4,%5,%6,%7}, {%8,%9}, {%0,%1,%2,%3};"
        : "+f"(c[0]), "+f"(c[1]), "+f"(c[2]), "+f"(c[3])
        : "r"(a[0]), "r"(a[1]), "r"(a[2]), "r"(a[3]), "r"(b[0]), "r"(b[1]));
}
__device__ __forceinline__ float gelu_exact(float x) {
    return 0.5f * x * (1.0f + erff(x * 0.70710678118654752f));
}

// ============================================================================
// Fused prepass (ONE launch):
//   blocks [0, XB)             : X fp32 -> fp16 copy (grid-stride float4)
//   blocks [XB, XB+W1B)        : W1 64x64 transpose+convert -> [N_STATE][N_EMBD]
//   blocks [XB+W1B, XB+W1B+W2B): W2 64x64 transpose+convert -> [N_EMBD][N_STATE]
// 64x64 transpose tiles: reads are 256B-coalesced rows; writes are FULL 128B
// sectors (64 halves per output row) — fixes the 50% write-sector waste that
// held the R12 prepass at 33% of DRAM spec.
// ============================================================================
#define XB_BLOCKS  2048
#define W1T_BX (N_STATE / 64)      // 64  (col tiles of W1 [1024][4096])
#define W1T_BY (N_EMBD  / 64)      // 16
#define W2T_BX (N_EMBD  / 64)      // 16  (col tiles of W2 [4096][1024])
#define W2T_BY (N_STATE / 64)      // 64
#define W1T_BLOCKS (W1T_BX * W1T_BY)   // 1024
#define W2T_BLOCKS (W2T_BX * W2T_BY)   // 1024
#define PRE_BLOCKS (XB_BLOCKS + W1T_BLOCKS + W2T_BLOCKS)  // 4096

__device__ __forceinline__ void transpose_tile64(const float* __restrict__ in,
                                                 __half* __restrict__ out,
                                                 int rows, int cols, int bx, int by,
                                                 int tx, int ty) {
    __shared__ float tile[64][65];
    // read: 64 rows x 64 floats (256B per row, coalesced float2)
    for (int r = ty; r < 64; r += 8) {
        float2 v = *reinterpret_cast<const float2*>(in + (size_t)(by + r) * cols + bx + 2 * tx);
        tile[r][2 * tx]     = v.x;
        tile[r][2 * tx + 1] = v.y;
    }
    __syncthreads();
    // write: 64 output rows x 64 halves (128B per row, coalesced half2)
    for (int r = ty; r < 64; r += 8) {
        __half2 h = __floats2half2_rn(tile[2 * tx][r], tile[2 * tx + 1][r]);
        *reinterpret_cast<__half2*>(out + (size_t)(bx + r) * rows + by + 2 * tx) = h;
    }
}

__global__ void __launch_bounds__(256, 2)
prepass_kernel(const float* __restrict__ x,  __half* __restrict__ Xh,
               const float* __restrict__ w1, __half* __restrict__ W1t,
               const float* __restrict__ w2, __half* __restrict__ W2t)
{
    const int b  = blockIdx.x;
    const int tx = threadIdx.x;
    const int ty = threadIdx.y;
    const int tid = ty * 32 + tx;

    if (b < XB_BLOCKS) {
        const int n4 = (M_TOTAL * N_EMBD) / 4;
        const int stride = XB_BLOCKS * 256;
        for (int i = b * 256 + tid; i < n4; i += stride) {
            float4 v = reinterpret_cast<const float4*>(x)[i];
            __half2* o = reinterpret_cast<__half2*>(Xh) + 2 * i;
            o[0] = __floats2half2_rn(v.x, v.y);
            o[1] = __floats2half2_rn(v.z, v.w);
        }
    } else if (b < XB_BLOCKS + W1T_BLOCKS) {
        const int bb = b - XB_BLOCKS;
        transpose_tile64(w1, W1t, N_EMBD, N_STATE,
                         (bb % W1T_BX) * 64, (bb / W1T_BX) * 64, tx, ty);
    } else {
        const int bb = b - XB_BLOCKS - W1T_BLOCKS;
        transpose_tile64(w2, W2t, N_STATE, N_EMBD,
                         (bb % W2T_BX) * 64, (bb / W2T_BX) * 64, tx, ty);
    }
}

// ============================================================================
// GEMM: out[M,N] = op(A[M,K] @ Bt[N,K]^T + bias)   — R6/R12 champion mainloop
// ============================================================================
template <int DO_GELU>
__global__ void __launch_bounds__(256, 2)
mlp_gemm_h(const __half* __restrict__ A, const __half* __restrict__ Bt,
           const float* __restrict__ bias, void* __restrict__ outp,
           int K, int N)
{
    extern __shared__ __half smem[];
    const uint32_t smem_base = smem_u32(smem);

    const int tid  = threadIdx.x;
    const int wid  = tid >> 5;
    const int lane = tid & 31;
    const int g    = lane >> 2;
    const int t4   = lane & 3;
    const int wm   = wid & 1;           // 2 warps in M (64 rows)
    const int wn   = wid >> 1;          // 4 warps in N (32 cols)

    const int m0 = blockIdx.y * CTA_M;
    const int n0 = blockIdx.x * CTA_N;
    const int num_kt = K / CTA_K;

    // per-lane ldmatrix offsets (bytes)
    const int mi = lane >> 3;
    const int r8 = lane & 7;
    const uint32_t a_lane = (uint32_t)(((mi & 1) * 8 + r8) * PITCH_B + (mi >> 1) * 16);
    const uint32_t b_lane = (uint32_t)(((mi >> 1) * 8 + r8) * PITCH_B + (mi & 1) * 16);
    const uint32_t aw_base = smem_base + (uint32_t)(wm * 64) * PITCH_B + a_lane;
    const uint32_t bw_base = smem_base + (uint32_t)(CTA_M + wn * 32) * PITCH_B + b_lane;

    auto load_stage = [&](int s, int kt) {
        uint32_t dstS = smem_base + (uint32_t)s * STAGE_BYTES;
        const __half* aG = A  + (size_t)m0 * K + kt * CTA_K;
        const __half* bG = Bt + (size_t)n0 * K + kt * CTA_K;
        #pragma unroll
        for (int i = 0; i < 8; i++) {
            int c   = tid + i * 256;
            int row = c >> 3, ch = c & 7;
            const __half* src = (row < CTA_M)
                ? aG + (size_t)row * K + ch * 8
                : bG + (size_t)(row - CTA_M) * K + ch * 8;
            cp_async16(dstS + (uint32_t)row * PITCH_B + (uint32_t)ch * 16, src);
        }
    };

    float acc[4][4][4];
    #pragma unroll
    for (int mt = 0; mt < 4; mt++)
        #pragma unroll
        for (int ni = 0; ni < 4; ni++)
            #pragma unroll
            for (int j = 0; j < 4; j++) acc[mt][ni][j] = 0.0f;

    load_stage(0, 0); cp_commit();
    load_stage(1, 1); cp_commit();

    int s_cur = 0, s_next = 2;
    for (int kt = 0; kt < num_kt; kt++) {
        cp_wait<STAGES - 2>();
        __syncthreads();

        if (kt + STAGES - 1 < num_kt) load_stage(s_next, kt + STAGES - 1);
        cp_commit();
        if (++s_next == STAGES) s_next = 0;

        const uint32_t aw = aw_base + (uint32_t)s_cur * STAGE_BYTES;
        const uint32_t bw = bw_base + (uint32_t)s_cur * STAGE_BYTES;
        if (++s_cur == STAGES) s_cur = 0;

        #pragma unroll
        for (int ks = 0; ks < 4; ks++) {
            const uint32_t ko = (uint32_t)(ks * 32);      // 16 halves = 32B
            uint32_t af[4][4];
            #pragma unroll
            for (int mt = 0; mt < 4; mt++)
                ldsm_x4(af[mt], aw + ko + (uint32_t)(mt * 16) * PITCH_B);
            uint32_t bf[4][2];
            #pragma unroll
            for (int np = 0; np < 2; np++) {
                uint32_t q[4];
                ldsm_x4(q, bw + ko + (uint32_t)(np * 16) * PITCH_B);
                bf[np * 2][0]     = q[0]; bf[np * 2][1]     = q[1];
                bf[np * 2 + 1][0] = q[2]; bf[np * 2 + 1][1] = q[3];
            }
            #pragma unroll
            for (int mt = 0; mt < 4; mt++)
                #pragma unroll
                for (int ni = 0; ni < 4; ni++)
                    mma_f16(acc[mt][ni], af[mt], bf[ni]);
        }
    }

    // -------- epilogue --------
    #pragma unroll
    for (int mt = 0; mt < 4; mt++) {
        const int row = m0 + wm * 64 + mt * 16 + g;
        #pragma unroll
        for (int ni = 0; ni < 4; ni++) {
            const int col = n0 + wn * 32 + ni * 8 + 2 * t4;
            const float2 bv = *reinterpret_cast<const float2*>(bias + col);
            float x0 = acc[mt][ni][0] + bv.x;
            float x1 = acc[mt][ni][1] + bv.y;
            float x2 = acc[mt][ni][2] + bv.x;
            float x3 = acc[mt][ni][3] + bv.y;
            if (DO_GELU) {
                __half* out = (__half*)outp;
                __half2 h01 = __floats2half2_rn(gelu_exact(x0), gelu_exact(x1));
                __half2 h23 = __floats2half2_rn(gelu_exact(x2), gelu_exact(x3));
                *reinterpret_cast<__half2*>(out + (size_t)row * N + col)       = h01;
                *reinterpret_cast<__half2*>(out + (size_t)(row + 8) * N + col) = h23;
            } else {
                float* out = (float*)outp;
                float2 v01 = {x0, x1}, v23 = {x2, x3};
                *reinterpret_cast<float2*>(out + (size_t)row * N + col)       = v01;
                *reinterpret_cast<float2*>(out + (size_t)(row + 8) * N + col) = v23;
            }
        }
    }
}

// ============================================================================
// Host
// ============================================================================
extern "C" void kernel_launch(void* const* d_in, const int* in_sizes, int n_in,
                              void* d_out, int out_size) {
    const float* x  = (const float*)d_in[0];
    const float* w1 = (const float*)d_in[1];
    const float* b1 = (const float*)d_in[2];
    const float* w2 = (const float*)d_in[3];
    const float* b2 = (const float*)d_in[4];
    float* out = (float*)d_out;

    __half *Xh, *W1t, *W2t, *H;
    cudaGetSymbolAddress((void**)&Xh,  g_Xh);
    cudaGetSymbolAddress((void**)&W1t, g_W1t);
    cudaGetSymbolAddress((void**)&W2t, g_W2t);
    cudaGetSymbolAddress((void**)&H,   g_H);

    cudaFuncSetAttribute((const void*)mlp_gemm_h<1>,
                         cudaFuncAttributeMaxDynamicSharedMemorySize, SMEM_BYTES);
    cudaFuncSetAttribute((const void*)mlp_gemm_h<0>,
                         cudaFuncAttributeMaxDynamicSharedMemorySize, SMEM_BYTES);

    // Fused prepass (one launch): X -> fp16; W1, W2 -> fp16 transposed [N][K]
    prepass_kernel<<<PRE_BLOCKS, dim3(32, 8)>>>(x, Xh, w1, W1t, w2, W2t);

    // GEMM1: H = fp16(GELU(X @ W1 + b1))    grid 32 x 64
    mlp_gemm_h<1><<<dim3(N_STATE / CTA_N, M_TOTAL / CTA_M), 256, SMEM_BYTES>>>(
        Xh, W1t, b1, H, N_EMBD, N_STATE);

    // GEMM2: out = H @ W2 + b2              grid 8 x 64
    mlp_gemm_h<0><<<dim3(N_EMBD / CTA_N, M_TOTAL / CTA_M), 256, SMEM_BYTES>>>(
        H, W2t, b2, out, N_STATE, N_EMBD);
}

// round 15
// speedup vs baseline: 1.1161x; 1.0229x over previous
#include <cuda_runtime.h>
#include <cuda_fp16.h>
#include <cstdint>
#include <math.h>

// ============================================================================
// Shapes
// ============================================================================
#define M_TOTAL 8192
#define N_EMBD  1024
#define N_STATE 4096

// CTA 128x128x64, 8 warps of 64x32, 2 CTAs/SM  (champion mainloop config)
#define CTA_M  128
#define CTA_N  128
#define CTA_K  64
#define STAGES 3

#define PITCH_B   144
#define ROWS_PER_STAGE (CTA_M + CTA_N)              // 256
#define STAGE_BYTES    (ROWS_PER_STAGE * PITCH_B)   // 36864
#define SMEM_BYTES     (STAGES * STAGE_BYTES)       // 110592

// Tile counts
#define G1_TILES ((M_TOTAL / CTA_M) * (N_STATE / CTA_N))   // 2048 (32 n-tiles/row)
#define G2_TILES ((M_TOTAL / CTA_M) * (N_EMBD  / CTA_N))   // 512  (8 n-tiles/row)
#define M_BLOCKS (M_TOTAL / CTA_M)                          // 64
#define G1_NPM   (N_STATE / CTA_N)                          // 32 tiles per row-block

// Scratch (static; no allocation allowed)
__device__ __half g_Xh [(size_t)M_TOTAL * N_EMBD];
__device__ __half g_W1t[(size_t)N_STATE * N_EMBD];
__device__ __half g_W2t[(size_t)N_EMBD * N_STATE];
__device__ __half g_H  [(size_t)M_TOTAL * N_STATE];
__device__ int    g_cnt[M_BLOCKS];                   // GEMM1 row-block arrival counters

// ============================================================================
// PTX helpers
// ============================================================================
__device__ __forceinline__ uint32_t smem_u32(const void* p) {
    uint32_t a;
    asm("{ .reg .u64 t; cvta.to.shared.u64 t, %1; cvt.u32.u64 %0, t; }" : "=r"(a) : "l"(p));
    return a;
}
__device__ __forceinline__ void cp_async16(uint32_t dst, const void* src) {
    asm volatile("cp.async.cg.shared.global [%0], [%1], 16;" :: "r"(dst), "l"(src));
}
__device__ __forceinline__ void cp_commit() {
    asm volatile("cp.async.commit_group;" ::: "memory");
}
template <int N>
__device__ __forceinline__ void cp_wait() {
    asm volatile("cp.async.wait_group %0;" :: "n"(N) : "memory");
}
__device__ __forceinline__ void ldsm_x4(uint32_t* r, uint32_t addr) {
    asm volatile("ldmatrix.sync.aligned.m8n8.x4.shared.b16 {%0,%1,%2,%3}, [%4];"
        : "=r"(r[0]), "=r"(r[1]), "=r"(r[2]), "=r"(r[3]) : "r"(addr));
}
__device__ __forceinline__ void mma_f16(float* c, const uint32_t* a, const uint32_t* b) {
    asm volatile(
        "mma.sync.aligned.m16n8k16.row.col.f32.f16.f16.f32 "
        "{%0,%1,%2,%3}, {%4,%5,%6,%7}, {%8,%9}, {%0,%1,%2,%3};"
        : "+f"(c[0]), "+f"(c[1]), "+f"(c[2]), "+f"(c[3])
        : "r"(a[0]), "r"(a[1]), "r"(a[2]), "r"(a[3]), "r"(b[0]), "r"(b[1]));
}
__device__ __forceinline__ float gelu_exact(float x) {
    return 0.5f * x * (1.0f + erff(x * 0.70710678118654752f));
}
__device__ __forceinline__ int ld_acquire_gpu(const int* p) {
    int v;
    asm volatile("ld.acquire.gpu.b32 %0, [%1];" : "=r"(v) : "l"(p) : "memory");
    return v;
}

// ============================================================================
// Fused prepass (ONE launch) — R14 version + counter zeroing
// ============================================================================
#define XB_BLOCKS  2048
#define W1T_BX (N_STATE / 64)
#define W1T_BY (N_EMBD  / 64)
#define W2T_BX (N_EMBD  / 64)
#define W2T_BY (N_STATE / 64)
#define W1T_BLOCKS (W1T_BX * W1T_BY)
#define W2T_BLOCKS (W2T_BX * W2T_BY)
#define PRE_BLOCKS (XB_BLOCKS + W1T_BLOCKS + W2T_BLOCKS)

__device__ __forceinline__ void transpose_tile64(const float* __restrict__ in,
                                                 __half* __restrict__ out,
                                                 int rows, int cols, int bx, int by,
                                                 int tx, int ty) {
    __shared__ float tile[64][65];
    for (int r = ty; r < 64; r += 8) {
        float2 v = *reinterpret_cast<const float2*>(in + (size_t)(by + r) * cols + bx + 2 * tx);
        tile[r][2 * tx]     = v.x;
        tile[r][2 * tx + 1] = v.y;
    }
    __syncthreads();
    for (int r = ty; r < 64; r += 8) {
        __half2 h = __floats2half2_rn(tile[2 * tx][r], tile[2 * tx + 1][r]);
        *reinterpret_cast<__half2*>(out + (size_t)(bx + r) * rows + by + 2 * tx) = h;
    }
}

__global__ void __launch_bounds__(256, 2)
prepass_kernel(const float* __restrict__ x,  __half* __restrict__ Xh,
               const float* __restrict__ w1, __half* __restrict__ W1t,
               const float* __restrict__ w2, __half* __restrict__ W2t)
{
    const int b  = blockIdx.x;
    const int tx = threadIdx.x;
    const int ty = threadIdx.y;
    const int tid = ty * 32 + tx;

    if (b == 0 && tid < M_BLOCKS) g_cnt[tid] = 0;    // reset dependency counters

    if (b < XB_BLOCKS) {
        const int n4 = (M_TOTAL * N_EMBD) / 4;
        const int stride = XB_BLOCKS * 256;
        for (int i = b * 256 + tid; i < n4; i += stride) {
            float4 v = reinterpret_cast<const float4*>(x)[i];
            __half2* o = reinterpret_cast<__half2*>(Xh) + 2 * i;
            o[0] = __floats2half2_rn(v.x, v.y);
            o[1] = __floats2half2_rn(v.z, v.w);
        }
    } else if (b < XB_BLOCKS + W1T_BLOCKS) {
        const int bb = b - XB_BLOCKS;
        transpose_tile64(w1, W1t, N_EMBD, N_STATE,
                         (bb % W1T_BX) * 64, (bb / W1T_BX) * 64, tx, ty);
    } else {
        const int bb = b - XB_BLOCKS - W1T_BLOCKS;
        transpose_tile64(w2, W2t, N_STATE, N_EMBD,
                         (bb % W2T_BX) * 64, (bb / W2T_BX) * 64, tx, ty);
    }
}

// ============================================================================
// Fused dual-GEMM kernel (champion mainloop, bid-dispatched):
//   bid <  G1_TILES : GEMM1 tile  H = fp16(GELU(Xh @ W1t^T + b1)); arrive cnt[m]
//   bid >= G1_TILES : GEMM2 tile  out = H @ W2t^T + b2; waits cnt[m]==32 first
// GEMM1 tiles are m-major (row m = bids 32m..32m+31) so rows complete early;
// GEMM2 tiles backfill the slots GEMM1's drain frees (recovers the wave tail).
// ============================================================================
__global__ void __launch_bounds__(256, 2)
fused_mlp_kernel(const float* __restrict__ b1, const float* __restrict__ b2,
                 float* __restrict__ out)
{
    extern __shared__ __half smem[];
    const uint32_t smem_base = smem_u32(smem);

    const int tid  = threadIdx.x;
    const int wid  = tid >> 5;
    const int lane = tid & 31;
    const int g    = lane >> 2;
    const int t4   = lane & 3;
    const int wm   = wid & 1;
    const int wn   = wid >> 1;

    const bool is_g1 = (blockIdx.x < G1_TILES);
    int m0, n0, num_kt, K, N;
    const __half *A, *Bt;
    const float* bias;
    if (is_g1) {
        const int t = blockIdx.x;
        m0 = (t >> 5) * CTA_M;          // m-major
        n0 = (t & 31) * CTA_N;
        K = N_EMBD;  N = N_STATE;  num_kt = N_EMBD / CTA_K;     // 16
        A = g_Xh;  Bt = g_W1t;  bias = b1;
    } else {
        const int u = blockIdx.x - G1_TILES;
        m0 = (u >> 3) * CTA_M;
        n0 = (u & 7) * CTA_N;
        K = N_STATE;  N = N_EMBD;  num_kt = N_STATE / CTA_K;    // 64
        A = g_H;  Bt = g_W2t;  bias = b2;

        // dependency: all 32 GEMM1 tiles of row-block m0/CTA_M must be done
        if (tid == 0) {
            const int* cp = &g_cnt[m0 / CTA_M];
            while (ld_acquire_gpu(cp) != G1_NPM) __nanosleep(200);
        }
        __syncthreads();
    }

    // per-lane ldmatrix offsets (bytes)
    const int mi = lane >> 3;
    const int r8 = lane & 7;
    const uint32_t a_lane = (uint32_t)(((mi & 1) * 8 + r8) * PITCH_B + (mi >> 1) * 16);
    const uint32_t b_lane = (uint32_t)(((mi >> 1) * 8 + r8) * PITCH_B + (mi & 1) * 16);
    const uint32_t aw_base = smem_base + (uint32_t)(wm * 64) * PITCH_B + a_lane;
    const uint32_t bw_base = smem_base + (uint32_t)(CTA_M + wn * 32) * PITCH_B + b_lane;

    auto load_stage = [&](int s, int kt) {
        uint32_t dstS = smem_base + (uint32_t)s * STAGE_BYTES;
        const __half* aG = A  + (size_t)m0 * K + kt * CTA_K;
        const __half* bG = Bt + (size_t)n0 * K + kt * CTA_K;
        #pragma unroll
        for (int i = 0; i < 8; i++) {
            int c   = tid + i * 256;
            int row = c >> 3, ch = c & 7;
            const __half* src = (row < CTA_M)
                ? aG + (size_t)row * K + ch * 8
                : bG + (size_t)(row - CTA_M) * K + ch * 8;
            cp_async16(dstS + (uint32_t)row * PITCH_B + (uint32_t)ch * 16, src);
        }
    };

    float acc[4][4][4];
    #pragma unroll
    for (int mt = 0; mt < 4; mt++)
        #pragma unroll
        for (int ni = 0; ni < 4; ni++)
            #pragma unroll
            for (int j = 0; j < 4; j++) acc[mt][ni][j] = 0.0f;

    load_stage(0, 0); cp_commit();
    load_stage(1, 1); cp_commit();

    int s_cur = 0, s_next = 2;
    for (int kt = 0; kt < num_kt; kt++) {
        cp_wait<STAGES - 2>();
        __syncthreads();

        if (kt + STAGES - 1 < num_kt) load_stage(s_next, kt + STAGES - 1);
        cp_commit();
        if (++s_next == STAGES) s_next = 0;

        const uint32_t aw = aw_base + (uint32_t)s_cur * STAGE_BYTES;
        const uint32_t bw = bw_base + (uint32_t)s_cur * STAGE_BYTES;
        if (++s_cur == STAGES) s_cur = 0;

        #pragma unroll
        for (int ks = 0; ks < 4; ks++) {
            const uint32_t ko = (uint32_t)(ks * 32);
            uint32_t af[4][4];
            #pragma unroll
            for (int mt = 0; mt < 4; mt++)
                ldsm_x4(af[mt], aw + ko + (uint32_t)(mt * 16) * PITCH_B);
            uint32_t bf[4][2];
            #pragma unroll
            for (int np = 0; np < 2; np++) {
                uint32_t q[4];
                ldsm_x4(q, bw + ko + (uint32_t)(np * 16) * PITCH_B);
                bf[np * 2][0]     = q[0]; bf[np * 2][1]     = q[1];
                bf[np * 2 + 1][0] = q[2]; bf[np * 2 + 1][1] = q[3];
            }
            #pragma unroll
            for (int mt = 0; mt < 4; mt++)
                #pragma unroll
                for (int ni = 0; ni < 4; ni++)
                    mma_f16(acc[mt][ni], af[mt], bf[ni]);
        }
    }

    // -------- epilogue --------
    #pragma unroll
    for (int mt = 0; mt < 4; mt++) {
        const int row = m0 + wm * 64 + mt * 16 + g;
        #pragma unroll
        for (int ni = 0; ni < 4; ni++) {
            const int col = n0 + wn * 32 + ni * 8 + 2 * t4;
            const float2 bv = *reinterpret_cast<const float2*>(bias + col);
            float x0 = acc[mt][ni][0] + bv.x;
            float x1 = acc[mt][ni][1] + bv.y;
            float x2 = acc[mt][ni][2] + bv.x;
            float x3 = acc[mt][ni][3] + bv.y;
            if (is_g1) {
                __half2 h01 = __floats2half2_rn(gelu_exact(x0), gelu_exact(x1));
                __half2 h23 = __floats2half2_rn(gelu_exact(x2), gelu_exact(x3));
                *reinterpret_cast<__half2*>(g_H + (size_t)row * N + col)       = h01;
                *reinterpret_cast<__half2*>(g_H + (size_t)(row + 8) * N + col) = h23;
            } else {
                float2 v01 = {x0, x1}, v23 = {x2, x3};
                *reinterpret_cast<float2*>(out + (size_t)row * N + col)       = v01;
                *reinterpret_cast<float2*>(out + (size_t)(row + 8) * N + col) = v23;
            }
        }
    }

    // GEMM1: publish row-block completion
    if (is_g1) {
        __syncthreads();                 // all warps' H stores issued
        if (tid == 0) {
            __threadfence();             // H visible GPU-wide before arrival
            atomicAdd(&g_cnt[m0 / CTA_M], 1);
        }
    }
}

// ============================================================================
// Host
// ============================================================================
extern "C" void kernel_launch(void* const* d_in, const int* in_sizes, int n_in,
                              void* d_out, int out_size) {
    const float* x  = (const float*)d_in[0];
    const float* w1 = (const float*)d_in[1];
    const float* b1 = (const float*)d_in[2];
    const float* w2 = (const float*)d_in[3];
    const float* b2 = (const float*)d_in[4];
    float* out = (float*)d_out;

    __half *Xh, *W1t, *W2t;
    cudaGetSymbolAddress((void**)&Xh,  g_Xh);
    cudaGetSymbolAddress((void**)&W1t, g_W1t);
    cudaGetSymbolAddress((void**)&W2t, g_W2t);

    cudaFuncSetAttribute((const void*)fused_mlp_kernel,
                         cudaFuncAttributeMaxDynamicSharedMemorySize, SMEM_BYTES);

    // Prepass (one launch): converts/transposes + zeroes dependency counters
    prepass_kernel<<<PRE_BLOCKS, dim3(32, 8)>>>(x, Xh, w1, W1t, w2, W2t);

    // Fused GEMM1 + GEMM2: 2048 + 512 CTAs, GEMM2 backfills GEMM1's drain
    fused_mlp_kernel<<<G1_TILES + G2_TILES, 256, SMEM_BYTES>>>(b1, b2, out);
}